// round 8
// baseline (speedup 1.0000x reference)
#include <cuda_runtime.h>
#include <cuda_bf16.h>
#include <stdint.h>

#define N_TOKENS_TOTAL 16384
#define D_PROJ 1024
#define EMB_SCALE 32.0f
#define MAX_TILES 136      // sum ceil(cnt_c/128) <= 128+3
#define NTHREADS 256
#define NS 3               // cp.async pipeline stages

// ---------------- scratch ----------------
__device__ int g_cnt[4];
__device__ int g_tok[4][N_TOKENS_TOTAL];
__device__ int g_loc[4][N_TOKENS_TOTAL];
__device__ int g_tile_c[MAX_TILES];
__device__ int g_tile_m0[MAX_TILES];
__device__ int g_total_tiles;

// pre-split proj scratch: layout [1024][K] per cluster, bf16 hi/lo
#define B_ELEMS (1024u * 1360u)
__device__ __nv_bfloat16 g_bhi[B_ELEMS];
__device__ __nv_bfloat16 g_blo[B_ELEMS];

__constant__ int c_K[4] = {1024, 256, 64, 16};
__constant__ unsigned c_BOFF[4] = {0u, 1024u*1024u, 1024u*1280u, 1024u*1344u};

// ---------------- helpers ----------------
__device__ __forceinline__ uint32_t smem_u32(const void* p) {
    uint32_t a;
    asm("{ .reg .u64 t; cvta.to.shared.u64 t, %1; cvt.u32.u64 %0, t; }" : "=r"(a) : "l"(p));
    return a;
}
__device__ __forceinline__ void ldsm4(uint32_t* r, uint32_t addr) {
    asm volatile("ldmatrix.sync.aligned.m8n8.x4.shared.b16 {%0,%1,%2,%3}, [%4];"
                 : "=r"(r[0]), "=r"(r[1]), "=r"(r[2]), "=r"(r[3]) : "r"(addr));
}
__device__ __forceinline__ void mma_bf16(float* c, const uint32_t* a,
                                         uint32_t b0, uint32_t b1) {
    asm volatile(
        "mma.sync.aligned.m16n8k16.row.col.f32.bf16.bf16.f32 "
        "{%0,%1,%2,%3}, {%4,%5,%6,%7}, {%8,%9}, {%0,%1,%2,%3};"
        : "+f"(c[0]), "+f"(c[1]), "+f"(c[2]), "+f"(c[3])
        : "r"(a[0]), "r"(a[1]), "r"(a[2]), "r"(a[3]), "r"(b0), "r"(b1));
}
__device__ __forceinline__ void cp16(uint32_t dst, const void* src, int sz) {
    asm volatile("cp.async.cg.shared.global [%0], [%1], 16, %2;"
                 :: "r"(dst), "l"(src), "r"(sz) : "memory");
}
#define CP_COMMIT() asm volatile("cp.async.commit_group;" ::: "memory")
#define CP_WAIT1()  asm volatile("cp.async.wait_group 1;" ::: "memory")

// A (fp32) smem: rows of 32 floats = 128B, 16B-granule swizzle
__device__ __forceinline__ uint32_t faddr(uint32_t base, int row, int k) {
    return base + (uint32_t)(row * 128) +
           ((uint32_t)(((k >> 2) ^ ((row & 3) << 1)) << 4)) + (uint32_t)((k & 3) * 4);
}
__device__ __forceinline__ float2 lds2(uint32_t addr) {
    float2 v;
    asm volatile("ld.shared.v2.f32 {%0,%1}, [%2];" : "=f"(v.x), "=f"(v.y) : "r"(addr));
    return v;
}
// B (bf16) smem: rows of 128B = [hi k32 | lo k32], XOR swizzle (R5-validated)
__device__ __forceinline__ uint32_t bswz(uint32_t base, int row, int kbyte) {
    return base + (((uint32_t)(row * 128 + kbyte)) ^ (uint32_t)((row & 7) << 4));
}
__device__ __forceinline__ void split2(float2 f, uint32_t& hi, uint32_t& lo) {
    __nv_bfloat162 h = __float22bfloat162_rn(f);
    float2 hf = __bfloat1622float2(h);
    float2 r = make_float2(f.x - hf.x, f.y - hf.y);
    __nv_bfloat162 l = __float22bfloat162_rn(r);
    hi = *reinterpret_cast<uint32_t*>(&h);
    lo = *reinterpret_cast<uint32_t*>(&l);
}

// ---------------- small kernels ----------------
__global__ void zero_kernel() {
    if (threadIdx.x < 4) g_cnt[threadIdx.x] = 0;
}
__global__ void bucket_kernel(const int* __restrict__ inp, int n) {
    int t = blockIdx.x * blockDim.x + threadIdx.x;
    if (t >= n) return;
    int v = inp[t];
    int c, l;
    if (v < 20000)       { c = 0; l = 0; }
    else if (v < 40000)  { c = 1; l = 20000; }
    else if (v < 200000) { c = 2; l = 40000; }
    else                 { c = 3; l = 200000; }
    int p = atomicAdd(&g_cnt[c], 1);
    g_tok[c][p] = t;
    g_loc[c][p] = v - l;
}
__global__ void plan_kernel() {
    __shared__ int offs[5];
    if (threadIdx.x == 0) {
        offs[0] = 0;
        for (int c = 0; c < 4; c++) offs[c + 1] = offs[c] + ((g_cnt[c] + 127) >> 7);
        g_total_tiles = offs[4];
    }
    __syncthreads();
    const int total = offs[4];
    for (int i = threadIdx.x; i < total; i += blockDim.x) {
        int c = 0;
        while (i >= offs[c + 1]) c++;
        g_tile_c[i] = c;
        g_tile_m0[i] = (i - offs[c]) << 7;
    }
}
// proj -> bf16 hi/lo (once; B is reused by ~131 tile rows)
__global__ void bconv_kernel(const float* __restrict__ p0, const float* __restrict__ p1,
                             const float* __restrict__ p2, const float* __restrict__ p3) {
    int c = blockIdx.y;
    const float* proj = c == 0 ? p0 : c == 1 ? p1 : c == 2 ? p2 : p3;
    unsigned base = c_BOFF[c];
    unsigned total = (unsigned)(1024 * c_K[c] / 2);
    unsigned stride = gridDim.x * blockDim.x;
    for (unsigned p = blockIdx.x * blockDim.x + threadIdx.x; p < total; p += stride) {
        unsigned e = p * 2;
        float2 f = *reinterpret_cast<const float2*>(proj + e);
        uint32_t hi, lo;
        split2(f, hi, lo);
        *reinterpret_cast<uint32_t*>(g_bhi + base + e) = hi;
        *reinterpret_cast<uint32_t*>(g_blo + base + e) = lo;
    }
}

// ---------------- fused cp.async-pipelined GEMM ----------------
// BK=32. Stage: A[128][32]f32 16KB + B[128 rows][hi k32|lo k32]bf16 16KB = 32KB; NS=3.
#define STG_A 0
#define STG_B 16384
#define STG_STRIDE 32768
#define SMEM_BYTES (NS * STG_STRIDE)

__global__ __launch_bounds__(NTHREADS, 2) void gemm_mma_kernel(
    const float* __restrict__ e0, const float* __restrict__ e1,
    const float* __restrict__ e2, const float* __restrict__ e3,
    float* __restrict__ out)
{
    extern __shared__ char smem[];
    const uint32_t sb = smem_u32(smem);
    __shared__ int s_loc[128];

    const int tile = blockIdx.y;
    if (tile >= g_total_tiles) return;

    const int cluster = g_tile_c[tile];
    const int m0 = g_tile_m0[tile];
    const int cnt = g_cnt[cluster];
    const int K = c_K[cluster];
    const int n0 = blockIdx.x * 128;
    const float* emb = cluster == 0 ? e0 : cluster == 1 ? e1 : cluster == 2 ? e2 : e3;
    const __nv_bfloat16* bhi = g_bhi + c_BOFF[cluster];
    const __nv_bfloat16* blo = g_blo + c_BOFF[cluster];

    const int tid  = threadIdx.x;
    const int lane = tid & 31;
    const int wid  = tid >> 5;
    const int mwarp = (wid & 3) * 32;
    const int nwarp = (wid >> 2) * 64;

    for (int i = tid; i < 128; i += NTHREADS) {
        const int r = m0 + i;
        s_loc[i] = (r < cnt) ? g_loc[cluster][r] : -1;
    }
    __syncthreads();

    const int nchunks = (K + 31) >> 5;

    auto issue = [&](int ic) {
        const int k0 = ic << 5;
        const int kc = (K - k0) < 32 ? (K - k0) : 32;   // 32 or 16
        const uint32_t bo = sb + (uint32_t)(ic % NS) * STG_STRIDE;
        // A: fp32, 16B granules (kc/4 per row)
        {
            const int lgn = (kc == 32) ? 3 : 2;
            const int ng = 1 << lgn;
            const int tot = 128 << lgn;
            for (int ci = tid; ci < tot; ci += NTHREADS) {
                const int row = ci >> lgn;
                const int g = ci & (ng - 1);
                const uint32_t sw = (uint32_t)(row * 128) +
                                    ((uint32_t)((g ^ ((row & 3) << 1)) << 4));
                const int gl = s_loc[row];
                const float* srcA = emb + ((gl >= 0 ? (size_t)gl : 0) * K + k0 + g * 4);
                cp16(bo + STG_A + sw, srcA, gl >= 0 ? 16 : 0);
            }
        }
        // B: bf16 hi|lo packed rows, granule h*4+j (j < kc/8)
        {
            const int jn = kc >> 3;                     // 4 or 2
            const int tot = 128 * 2 * jn;
            for (int ci = tid; ci < tot; ci += NTHREADS) {
                const int row = ci / (2 * jn);
                const int rem = ci - row * 2 * jn;
                const int h = rem / jn;                 // 0=hi, 1=lo
                const int j = rem - h * jn;
                const int g = h * 4 + j;
                const uint32_t sw = (uint32_t)((row * 128 + g * 16) ^ ((row & 7) << 4));
                const __nv_bfloat16* src =
                    (h == 0 ? bhi : blo) + (size_t)(n0 + row) * K + k0 + j * 8;
                cp16(bo + STG_B + sw, src, 16);
            }
        }
    };

    for (int s = 0; s < NS - 1; s++) {
        if (s < nchunks) issue(s);
        CP_COMMIT();
    }

    float acc[2][8][4] = {};

    for (int ic = 0; ic < nchunks; ic++) {
        CP_WAIT1();
        __syncthreads();
        if (ic + NS - 1 < nchunks) issue(ic + NS - 1);
        CP_COMMIT();

        const int k0 = ic << 5;
        const int kc = (K - k0) < 32 ? (K - k0) : 32;
        const uint32_t bo = sb + (uint32_t)(ic % NS) * STG_STRIDE;
        const int ksteps = kc >> 4;            // 2 or 1

        for (int ks = 0; ks < ksteps; ks++) {
            // A fragments (hi+lo) via LDS + in-register split
            const int kb = ks * 16 + (lane & 3) * 2;
            uint32_t ah[2][4], al[2][4];
#pragma unroll
            for (int mt = 0; mt < 2; mt++) {
                const int r = mwarp + mt * 16 + (lane >> 2);
                split2(lds2(faddr(bo + STG_A, r,     kb)),     ah[mt][0], al[mt][0]);
                split2(lds2(faddr(bo + STG_A, r + 8, kb)),     ah[mt][1], al[mt][1]);
                split2(lds2(faddr(bo + STG_A, r,     kb + 8)), ah[mt][2], al[mt][2]);
                split2(lds2(faddr(bo + STG_A, r + 8, kb + 8)), ah[mt][3], al[mt][3]);
            }
            // B fragments via ldmatrix (pre-split bf16)
            const int broff = (lane & 7) + ((lane >> 4) << 3);
            const int bkb   = ks * 32 + ((lane >> 3) & 1) * 16;
#pragma unroll
            for (int ng = 0; ng < 4; ng++) {
                uint32_t bh[4], bl[4];
                const int row = nwarp + ng * 16 + broff;
                ldsm4(bh, bswz(bo + STG_B, row, bkb));
                ldsm4(bl, bswz(bo + STG_B, row, 64 + bkb));
#pragma unroll
                for (int mt = 0; mt < 2; mt++) {
                    mma_bf16(acc[mt][2 * ng + 0], ah[mt], bh[0], bh[1]);
                    mma_bf16(acc[mt][2 * ng + 0], ah[mt], bl[0], bl[1]);
                    mma_bf16(acc[mt][2 * ng + 0], al[mt], bh[0], bh[1]);
                    mma_bf16(acc[mt][2 * ng + 1], ah[mt], bh[2], bh[3]);
                    mma_bf16(acc[mt][2 * ng + 1], ah[mt], bl[2], bl[3]);
                    mma_bf16(acc[mt][2 * ng + 1], al[mt], bh[2], bh[3]);
                }
            }
        }
        __syncthreads();
    }

    // epilogue: scale + scatter
#pragma unroll
    for (int mt = 0; mt < 2; mt++) {
        const int r0 = m0 + mwarp + mt * 16 + (lane >> 2);
        const int r1 = r0 + 8;
        float* q0 = nullptr;
        float* q1 = nullptr;
        if (r0 < cnt) q0 = out + (size_t)g_tok[cluster][r0] * D_PROJ + n0 + nwarp + (lane & 3) * 2;
        if (r1 < cnt) q1 = out + (size_t)g_tok[cluster][r1] * D_PROJ + n0 + nwarp + (lane & 3) * 2;
#pragma unroll
        for (int nt = 0; nt < 8; nt++) {
            if (q0) *reinterpret_cast<float2*>(q0 + nt * 8) =
                make_float2(acc[mt][nt][0] * EMB_SCALE, acc[mt][nt][1] * EMB_SCALE);
            if (q1) *reinterpret_cast<float2*>(q1 + nt * 8) =
                make_float2(acc[mt][nt][2] * EMB_SCALE, acc[mt][nt][3] * EMB_SCALE);
        }
    }
}

// ---------------- launch ----------------
extern "C" void kernel_launch(void* const* d_in, const int* in_sizes, int n_in,
                              void* d_out, int out_size) {
    const int* inp = (const int*)d_in[0];
    const float* emb[4];
    const float* proj[4];

    if (n_in >= 9 && in_sizes[2] == 1024 * 1024) {
        for (int i = 0; i < 4; i++) {
            emb[i]  = (const float*)d_in[1 + 2 * i];
            proj[i] = (const float*)d_in[2 + 2 * i];
        }
    } else {
        for (int i = 0; i < 4; i++) {
            emb[i]  = (const float*)d_in[1 + i];
            proj[i] = (const float*)d_in[5 + i];
        }
    }

    float* out = (float*)d_out;
    const int n_tok = in_sizes[0];

    cudaFuncSetAttribute(gemm_mma_kernel,
                         cudaFuncAttributeMaxDynamicSharedMemorySize, SMEM_BYTES);

    zero_kernel<<<1, 32>>>();
    bucket_kernel<<<(n_tok + 255) / 256, 256>>>(inp, n_tok);
    plan_kernel<<<1, 128>>>();
    bconv_kernel<<<dim3(256, 4), 256>>>(proj[0], proj[1], proj[2], proj[3]);

    dim3 grid(D_PROJ / 128, MAX_TILES);
    gemm_mma_kernel<<<grid, NTHREADS, SMEM_BYTES>>>(emb[0], emb[1], emb[2], emb[3], out);
}

// round 9
// speedup vs baseline: 1.2224x; 1.2224x over previous
#include <cuda_runtime.h>
#include <cuda_bf16.h>
#include <stdint.h>

#define N_TOKENS_TOTAL 16384
#define D_PROJ 1024
#define EMB_SCALE 32.0f
#define MAX_TILES 136
#define NTHREADS 256
#define NS 3

// ---------------- scratch ----------------
__device__ int g_cnt[4];
__device__ int g_tok[4][N_TOKENS_TOTAL];
__device__ int g_loc[4][N_TOKENS_TOTAL];
__device__ int g_tile_c[MAX_TILES];
__device__ int g_tile_m0[MAX_TILES];
__device__ int g_total_tiles;

// pre-split bf16 scratch. A: compacted gathered rows, worst-case 16384 rows/cluster.
#define A_ELEMS (16384u * 1360u)
#define B_ELEMS (1024u * 1360u)
__device__ __nv_bfloat16 g_ahi[A_ELEMS];
__device__ __nv_bfloat16 g_alo[A_ELEMS];
__device__ __nv_bfloat16 g_bhi[B_ELEMS];
__device__ __nv_bfloat16 g_blo[B_ELEMS];

__constant__ int c_K[4]    = {1024, 256, 64, 16};
__constant__ int c_logK[4] = {10, 8, 6, 4};
__constant__ unsigned c_AOFF[4] = {0u, 16384u*1024u, 16384u*1280u, 16384u*1344u};
__constant__ unsigned c_BOFF[4] = {0u, 1024u*1024u, 1024u*1280u, 1024u*1344u};

// ---------------- helpers ----------------
__device__ __forceinline__ uint32_t smem_u32(const void* p) {
    uint32_t a;
    asm("{ .reg .u64 t; cvta.to.shared.u64 t, %1; cvt.u32.u64 %0, t; }" : "=r"(a) : "l"(p));
    return a;
}
__device__ __forceinline__ void ldsm4(uint32_t* r, uint32_t addr) {
    asm volatile("ldmatrix.sync.aligned.m8n8.x4.shared.b16 {%0,%1,%2,%3}, [%4];"
                 : "=r"(r[0]), "=r"(r[1]), "=r"(r[2]), "=r"(r[3]) : "r"(addr));
}
__device__ __forceinline__ void mma_bf16(float* c, const uint32_t* a,
                                         uint32_t b0, uint32_t b1) {
    asm volatile(
        "mma.sync.aligned.m16n8k16.row.col.f32.bf16.bf16.f32 "
        "{%0,%1,%2,%3}, {%4,%5,%6,%7}, {%8,%9}, {%0,%1,%2,%3};"
        : "+f"(c[0]), "+f"(c[1]), "+f"(c[2]), "+f"(c[3])
        : "r"(a[0]), "r"(a[1]), "r"(a[2]), "r"(a[3]), "r"(b0), "r"(b1));
}
__device__ __forceinline__ void cp16(uint32_t dst, const void* src) {
    asm volatile("cp.async.cg.shared.global [%0], [%1], 16;"
                 :: "r"(dst), "l"(src) : "memory");
}
#define CP_COMMIT() asm volatile("cp.async.commit_group;" ::: "memory")
#define CP_WAIT1()  asm volatile("cp.async.wait_group 1;" ::: "memory")

// bf16 smem rows: 128B = [hi k32 (64B) | lo k32 (64B)], XOR 16B-granule swizzle
__device__ __forceinline__ uint32_t bswz(uint32_t base, int row, int kbyte) {
    return base + (((uint32_t)(row * 128 + kbyte)) ^ (uint32_t)((row & 7) << 4));
}
__device__ __forceinline__ void split2(float2 f, uint32_t& hi, uint32_t& lo) {
    __nv_bfloat162 h = __float22bfloat162_rn(f);
    float2 hf = __bfloat1622float2(h);
    float2 r = make_float2(f.x - hf.x, f.y - hf.y);
    __nv_bfloat162 l = __float22bfloat162_rn(r);
    hi = *reinterpret_cast<uint32_t*>(&h);
    lo = *reinterpret_cast<uint32_t*>(&l);
}

// ---------------- small kernels ----------------
__global__ void zero_kernel() {
    if (threadIdx.x < 4) g_cnt[threadIdx.x] = 0;
}
__global__ void bucket_kernel(const int* __restrict__ inp, int n) {
    int t = blockIdx.x * blockDim.x + threadIdx.x;
    if (t >= n) return;
    int v = inp[t];
    int c, l;
    if (v < 20000)       { c = 0; l = 0; }
    else if (v < 40000)  { c = 1; l = 20000; }
    else if (v < 200000) { c = 2; l = 40000; }
    else                 { c = 3; l = 200000; }
    int p = atomicAdd(&g_cnt[c], 1);
    g_tok[c][p] = t;
    g_loc[c][p] = v - l;
}
__global__ void plan_kernel() {
    __shared__ int offs[5];
    if (threadIdx.x == 0) {
        offs[0] = 0;
        for (int c = 0; c < 4; c++) offs[c + 1] = offs[c] + ((g_cnt[c] + 127) >> 7);
        g_total_tiles = offs[4];
    }
    __syncthreads();
    const int total = offs[4];
    for (int i = threadIdx.x; i < total; i += blockDim.x) {
        int c = 0;
        while (i >= offs[c + 1]) c++;
        g_tile_c[i] = c;
        g_tile_m0[i] = (i - offs[c]) << 7;
    }
}
// proj -> bf16 hi/lo
__global__ void bconv_kernel(const float* __restrict__ p0, const float* __restrict__ p1,
                             const float* __restrict__ p2, const float* __restrict__ p3) {
    int c = blockIdx.y;
    const float* proj = c == 0 ? p0 : c == 1 ? p1 : c == 2 ? p2 : p3;
    unsigned base = c_BOFF[c];
    unsigned total = (unsigned)(1024 * c_K[c] / 2);
    unsigned stride = gridDim.x * blockDim.x;
    for (unsigned p = blockIdx.x * blockDim.x + threadIdx.x; p < total; p += stride) {
        unsigned e = p * 2;
        float2 f = *reinterpret_cast<const float2*>(proj + e);
        uint32_t hi, lo;
        split2(f, hi, lo);
        *reinterpret_cast<uint32_t*>(g_bhi + base + e) = hi;
        *reinterpret_cast<uint32_t*>(g_blo + base + e) = lo;
    }
}
// gathered emb rows -> compacted bf16 hi/lo
__global__ void aconv_kernel(const float* __restrict__ e0, const float* __restrict__ e1,
                             const float* __restrict__ e2, const float* __restrict__ e3) {
    int c = blockIdx.y;
    const float* emb = c == 0 ? e0 : c == 1 ? e1 : c == 2 ? e2 : e3;
    int K = c_K[c], lk = c_logK[c];
    int cnt = g_cnt[c];
    unsigned base = c_AOFF[c];
    unsigned total = (unsigned)(((long)cnt * K) >> 1);
    unsigned stride = gridDim.x * blockDim.x;
    for (unsigned p = blockIdx.x * blockDim.x + threadIdx.x; p < total; p += stride) {
        unsigned e = p * 2;
        int r = (int)(e >> lk);
        int k = (int)(e & (unsigned)(K - 1));
        int gl = g_loc[c][r];
        float2 f = *reinterpret_cast<const float2*>(emb + (size_t)gl * K + k);
        uint32_t hi, lo;
        split2(f, hi, lo);
        unsigned o = base + (unsigned)r * (unsigned)K + (unsigned)k;
        *reinterpret_cast<uint32_t*>(g_ahi + o) = hi;
        *reinterpret_cast<uint32_t*>(g_alo + o) = lo;
    }
}

// ---------------- all-bf16 cp.async-pipelined LDSM GEMM ----------------
// BK=32. Stage: A[128 rows][hi32|lo32] 16KB + B same 16KB = 32KB; NS=3 -> 96KB, 2 CTA/SM.
#define STG_A 0
#define STG_B 16384
#define STG_STRIDE 32768
#define SMEM_BYTES (NS * STG_STRIDE)

__global__ __launch_bounds__(NTHREADS, 2) void gemm_mma_kernel(float* __restrict__ out) {
    extern __shared__ char smem[];
    const uint32_t sb = smem_u32(smem);

    const int tile = blockIdx.y;
    if (tile >= g_total_tiles) return;

    const int cluster = g_tile_c[tile];
    const int m0 = g_tile_m0[tile];
    const int cnt = g_cnt[cluster];
    const int K = c_K[cluster];
    const int n0 = blockIdx.x * 128;

    const __nv_bfloat16* ahi = g_ahi + c_AOFF[cluster] + (size_t)m0 * K;
    const __nv_bfloat16* alo = g_alo + c_AOFF[cluster] + (size_t)m0 * K;
    const __nv_bfloat16* bhi = g_bhi + c_BOFF[cluster] + (size_t)n0 * K;
    const __nv_bfloat16* blo = g_blo + c_BOFF[cluster] + (size_t)n0 * K;

    const int tid  = threadIdx.x;
    const int lane = tid & 31;
    const int wid  = tid >> 5;
    const int mwarp = (wid & 3) * 32;
    const int nwarp = (wid >> 2) * 64;

    const int nchunks = (K + 31) >> 5;

    // stage chunk ic into buffer ic%NS. Granule g: 0-3 = hi j=g, 4-7 = lo j=g-4.
    auto issue = [&](int ic) {
        const int k0 = ic << 5;
        const uint32_t bo = sb + (uint32_t)(ic % NS) * STG_STRIDE;
        if (K - k0 >= 32) {
            // 8 granules/row, 1024 cp16 per matrix
            for (int ci = tid; ci < 1024; ci += NTHREADS) {
                const int row = ci >> 3;
                const int g = ci & 7;
                const uint32_t sw = (uint32_t)((row * 128 + g * 16) ^ ((row & 7) << 4));
                const size_t src = (size_t)row * K + k0 + (g & 3) * 8;
                cp16(bo + STG_A + sw, ((g < 4) ? ahi : alo) + src);
                cp16(bo + STG_B + sw, ((g < 4) ? bhi : blo) + src);
            }
        } else {
            // kc=16: granules {0,1,4,5}; 4/row
            for (int ci = tid; ci < 512; ci += NTHREADS) {
                const int row = ci >> 2;
                const int rem = ci & 3;
                const int h = rem >> 1;       // 0=hi 1=lo
                const int j = rem & 1;
                const int g = h * 4 + j;
                const uint32_t sw = (uint32_t)((row * 128 + g * 16) ^ ((row & 7) << 4));
                const size_t src = (size_t)row * K + k0 + j * 8;
                cp16(bo + STG_A + sw, (h == 0 ? ahi : alo) + src);
                cp16(bo + STG_B + sw, (h == 0 ? bhi : blo) + src);
            }
        }
    };

    for (int s = 0; s < NS - 1; s++) {
        if (s < nchunks) issue(s);
        CP_COMMIT();
    }

    float acc[2][8][4] = {};

    for (int ic = 0; ic < nchunks; ic++) {
        CP_WAIT1();
        __syncthreads();
        if (ic + NS - 1 < nchunks) issue(ic + NS - 1);
        CP_COMMIT();

        const int k0 = ic << 5;
        const int kc = (K - k0) < 32 ? (K - k0) : 32;
        const uint32_t bo = sb + (uint32_t)(ic % NS) * STG_STRIDE;
        const int ksteps = kc >> 4;

        for (int ks = 0; ks < ksteps; ks++) {
            // A fragments via ldmatrix (hi + lo)
            const int arow = lane & 15;
            const int akb  = ks * 32 + (lane >> 4) * 16;
            uint32_t ah[2][4], al[2][4];
#pragma unroll
            for (int mt = 0; mt < 2; mt++) {
                const int row = mwarp + mt * 16 + arow;
                ldsm4(ah[mt], bswz(bo + STG_A, row, akb));
                ldsm4(al[mt], bswz(bo + STG_A, row, 64 + akb));
            }
            // B fragments via ldmatrix
            const int broff = (lane & 7) + ((lane >> 4) << 3);
            const int bkb   = ks * 32 + ((lane >> 3) & 1) * 16;
#pragma unroll
            for (int ng = 0; ng < 4; ng++) {
                uint32_t bh[4], bl[4];
                const int row = nwarp + ng * 16 + broff;
                ldsm4(bh, bswz(bo + STG_B, row, bkb));
                ldsm4(bl, bswz(bo + STG_B, row, 64 + bkb));
#pragma unroll
                for (int mt = 0; mt < 2; mt++) {
                    mma_bf16(acc[mt][2 * ng + 0], ah[mt], bh[0], bh[1]);
                    mma_bf16(acc[mt][2 * ng + 0], ah[mt], bl[0], bl[1]);
                    mma_bf16(acc[mt][2 * ng + 0], al[mt], bh[0], bh[1]);
                    mma_bf16(acc[mt][2 * ng + 1], ah[mt], bh[2], bh[3]);
                    mma_bf16(acc[mt][2 * ng + 1], ah[mt], bl[2], bl[3]);
                    mma_bf16(acc[mt][2 * ng + 1], al[mt], bh[2], bh[3]);
                }
            }
        }
        __syncthreads();
    }

    // epilogue: scale + scatter
#pragma unroll
    for (int mt = 0; mt < 2; mt++) {
        const int r0 = m0 + mwarp + mt * 16 + (lane >> 2);
        const int r1 = r0 + 8;
        float* q0 = nullptr;
        float* q1 = nullptr;
        if (r0 < cnt) q0 = out + (size_t)g_tok[cluster][r0] * D_PROJ + n0 + nwarp + (lane & 3) * 2;
        if (r1 < cnt) q1 = out + (size_t)g_tok[cluster][r1] * D_PROJ + n0 + nwarp + (lane & 3) * 2;
#pragma unroll
        for (int nt = 0; nt < 8; nt++) {
            if (q0) *reinterpret_cast<float2*>(q0 + nt * 8) =
                make_float2(acc[mt][nt][0] * EMB_SCALE, acc[mt][nt][1] * EMB_SCALE);
            if (q1) *reinterpret_cast<float2*>(q1 + nt * 8) =
                make_float2(acc[mt][nt][2] * EMB_SCALE, acc[mt][nt][3] * EMB_SCALE);
        }
    }
}

// ---------------- launch ----------------
extern "C" void kernel_launch(void* const* d_in, const int* in_sizes, int n_in,
                              void* d_out, int out_size) {
    const int* inp = (const int*)d_in[0];
    const float* emb[4];
    const float* proj[4];

    if (n_in >= 9 && in_sizes[2] == 1024 * 1024) {
        for (int i = 0; i < 4; i++) {
            emb[i]  = (const float*)d_in[1 + 2 * i];
            proj[i] = (const float*)d_in[2 + 2 * i];
        }
    } else {
        for (int i = 0; i < 4; i++) {
            emb[i]  = (const float*)d_in[1 + i];
            proj[i] = (const float*)d_in[5 + i];
        }
    }

    float* out = (float*)d_out;
    const int n_tok = in_sizes[0];

    cudaFuncSetAttribute(gemm_mma_kernel,
                         cudaFuncAttributeMaxDynamicSharedMemorySize, SMEM_BYTES);

    zero_kernel<<<1, 32>>>();
    bucket_kernel<<<(n_tok + 255) / 256, 256>>>(inp, n_tok);
    plan_kernel<<<1, 128>>>();
    bconv_kernel<<<dim3(256, 4), 256>>>(proj[0], proj[1], proj[2], proj[3]);
    aconv_kernel<<<dim3(256, 4), 256>>>(emb[0], emb[1], emb[2], emb[3]);

    dim3 grid(D_PROJ / 128, MAX_TILES);
    gemm_mma_kernel<<<grid, NTHREADS, SMEM_BYTES>>>(out);
}

// round 10
// speedup vs baseline: 1.5167x; 1.2407x over previous
#include <cuda_runtime.h>
#include <cuda_bf16.h>
#include <stdint.h>

#define N_TOKENS_TOTAL 16384
#define D_PROJ 1024
#define EMB_SCALE 32.0f
#define MAX_TILES 136
#define NTHREADS 256
#define NS 3

// ---------------- scratch ----------------
__device__ int g_cnt[4];
__device__ int g_tok[4][N_TOKENS_TOTAL];
__device__ int g_loc[4][N_TOKENS_TOTAL];
__device__ int g_tile_c[MAX_TILES];
__device__ int g_tile_m0[MAX_TILES];
__device__ int g_total_tiles;

#define A_ELEMS (16384u * 1360u)
#define B_ELEMS (1024u * 1360u)
__device__ __nv_bfloat16 g_ahi[A_ELEMS];
__device__ __nv_bfloat16 g_alo[A_ELEMS];
__device__ __nv_bfloat16 g_bhi[B_ELEMS];
__device__ __nv_bfloat16 g_blo[B_ELEMS];

__constant__ int c_K[4]    = {1024, 256, 64, 16};
__constant__ int c_logK[4] = {10, 8, 6, 4};
__constant__ unsigned c_AOFF[4] = {0u, 16384u*1024u, 16384u*1280u, 16384u*1344u};
__constant__ unsigned c_BOFF[4] = {0u, 1024u*1024u, 1024u*1280u, 1024u*1344u};

// ---------------- helpers ----------------
__device__ __forceinline__ uint32_t smem_u32(const void* p) {
    uint32_t a;
    asm("{ .reg .u64 t; cvta.to.shared.u64 t, %1; cvt.u32.u64 %0, t; }" : "=r"(a) : "l"(p));
    return a;
}
__device__ __forceinline__ void ldsm4(uint32_t* r, uint32_t addr) {
    asm volatile("ldmatrix.sync.aligned.m8n8.x4.shared.b16 {%0,%1,%2,%3}, [%4];"
                 : "=r"(r[0]), "=r"(r[1]), "=r"(r[2]), "=r"(r[3]) : "r"(addr));
}
__device__ __forceinline__ void mma_bf16(float* c, const uint32_t* a,
                                         uint32_t b0, uint32_t b1) {
    asm volatile(
        "mma.sync.aligned.m16n8k16.row.col.f32.bf16.bf16.f32 "
        "{%0,%1,%2,%3}, {%4,%5,%6,%7}, {%8,%9}, {%0,%1,%2,%3};"
        : "+f"(c[0]), "+f"(c[1]), "+f"(c[2]), "+f"(c[3])
        : "r"(a[0]), "r"(a[1]), "r"(a[2]), "r"(a[3]), "r"(b0), "r"(b1));
}
__device__ __forceinline__ void cp16(uint32_t dst, const void* src) {
    asm volatile("cp.async.cg.shared.global [%0], [%1], 16;"
                 :: "r"(dst), "l"(src) : "memory");
}
#define CP_COMMIT() asm volatile("cp.async.commit_group;" ::: "memory")
#define CP_WAIT1()  asm volatile("cp.async.wait_group 1;" ::: "memory")

__device__ __forceinline__ uint32_t bswz(uint32_t base, int row, int kbyte) {
    return base + (((uint32_t)(row * 128 + kbyte)) ^ (uint32_t)((row & 7) << 4));
}
__device__ __forceinline__ void split2(float2 f, uint32_t& hi, uint32_t& lo) {
    __nv_bfloat162 h = __float22bfloat162_rn(f);
    float2 hf = __bfloat1622float2(h);
    float2 r = make_float2(f.x - hf.x, f.y - hf.y);
    __nv_bfloat162 l = __float22bfloat162_rn(r);
    hi = *reinterpret_cast<uint32_t*>(&h);
    lo = *reinterpret_cast<uint32_t*>(&l);
}

// ---------------- kernel 1: zero ----------------
__global__ void zero_kernel() {
    if (threadIdx.x < 4) g_cnt[threadIdx.x] = 0;
}

// ---------------- kernel 2: bucket (block-aggregated atomics) ----------------
__global__ void bucket_kernel(const int* __restrict__ inp, int n) {
    __shared__ int s_cnt[4];
    __shared__ int s_base[4];
    const int t = blockIdx.x * blockDim.x + threadIdx.x;
    if (threadIdx.x < 4) s_cnt[threadIdx.x] = 0;
    __syncthreads();
    int v = 0, c = 0, l = 0, rank = 0;
    const bool valid = t < n;
    if (valid) {
        v = inp[t];
        if (v < 20000)       { c = 0; l = 0; }
        else if (v < 40000)  { c = 1; l = 20000; }
        else if (v < 200000) { c = 2; l = 40000; }
        else                 { c = 3; l = 200000; }
        rank = atomicAdd(&s_cnt[c], 1);
    }
    __syncthreads();
    if (threadIdx.x < 4)
        s_base[threadIdx.x] = atomicAdd(&g_cnt[threadIdx.x], s_cnt[threadIdx.x]);
    __syncthreads();
    if (valid) {
        const int p = s_base[c] + rank;
        g_tok[c][p] = t;
        g_loc[c][p] = v - l;
    }
}

// ---------------- kernel 3: fused conversions + plan ----------------
// gridDim.y: 0..3 = proj cluster y; 4..7 = gathered emb cluster y-4.
// block (0,0) additionally builds the tile plan.
__global__ void conv_kernel(
    const float* __restrict__ e0, const float* __restrict__ e1,
    const float* __restrict__ e2, const float* __restrict__ e3,
    const float* __restrict__ p0, const float* __restrict__ p1,
    const float* __restrict__ p2, const float* __restrict__ p3)
{
    // ---- plan (one block) ----
    if (blockIdx.y == 0 && blockIdx.x == 0) {
        __shared__ int offs[5];
        if (threadIdx.x == 0) {
            offs[0] = 0;
            for (int c = 0; c < 4; c++) offs[c + 1] = offs[c] + ((g_cnt[c] + 127) >> 7);
            g_total_tiles = offs[4];
        }
        __syncthreads();
        const int total = offs[4];
        for (int i = threadIdx.x; i < total; i += blockDim.x) {
            int c = 0;
            while (i >= offs[c + 1]) c++;
            g_tile_c[i] = c;
            g_tile_m0[i] = (i - offs[c]) << 7;
        }
    }

    const int y = blockIdx.y;
    const unsigned stride = gridDim.x * blockDim.x;
    const unsigned t0 = blockIdx.x * blockDim.x + threadIdx.x;

    if (y < 4) {
        // ---- B: proj -> bf16 hi/lo, 4 elems/thread ----
        const int c = y;
        const float* proj = c == 0 ? p0 : c == 1 ? p1 : c == 2 ? p2 : p3;
        const unsigned base = c_BOFF[c];
        const unsigned nq = (unsigned)(1024 * c_K[c]) >> 2;
        for (unsigned q = t0; q < nq; q += stride) {
            const unsigned e = q << 2;
            const float4 f = *reinterpret_cast<const float4*>(proj + e);
            uint2 hi, lo;
            split2(make_float2(f.x, f.y), hi.x, lo.x);
            split2(make_float2(f.z, f.w), hi.y, lo.y);
            *reinterpret_cast<uint2*>(g_bhi + base + e) = hi;
            *reinterpret_cast<uint2*>(g_blo + base + e) = lo;
        }
    } else {
        // ---- A: gathered emb rows -> compacted bf16 hi/lo, 4 elems/thread ----
        const int c = y - 4;
        const float* emb = c == 0 ? e0 : c == 1 ? e1 : c == 2 ? e2 : e3;
        const int K = c_K[c], lk = c_logK[c];
        const int cnt = g_cnt[c];
        const unsigned base = c_AOFF[c];
        const unsigned nq = (unsigned)(((long)cnt * K) >> 2);
        for (unsigned q = t0; q < nq; q += stride) {
            const unsigned e = q << 2;
            const int r = (int)(e >> lk);
            const int k = (int)(e & (unsigned)(K - 1));
            const int gl = g_loc[c][r];
            const float4 f = *reinterpret_cast<const float4*>(emb + (size_t)gl * K + k);
            uint2 hi, lo;
            split2(make_float2(f.x, f.y), hi.x, lo.x);
            split2(make_float2(f.z, f.w), hi.y, lo.y);
            const unsigned o = base + (unsigned)r * (unsigned)K + (unsigned)k;
            *reinterpret_cast<uint2*>(g_ahi + o) = hi;
            *reinterpret_cast<uint2*>(g_alo + o) = lo;
        }
    }
}

// ---------------- kernel 4: all-bf16 cp.async-pipelined LDSM GEMM ----------------
#define STG_A 0
#define STG_B 16384
#define STG_STRIDE 32768
#define SMEM_BYTES (NS * STG_STRIDE)

__global__ __launch_bounds__(NTHREADS, 2) void gemm_mma_kernel(float* __restrict__ out) {
    extern __shared__ char smem[];
    const uint32_t sb = smem_u32(smem);

    const int tile = blockIdx.y;
    if (tile >= g_total_tiles) return;

    const int cluster = g_tile_c[tile];
    const int m0 = g_tile_m0[tile];
    const int cnt = g_cnt[cluster];
    const int K = c_K[cluster];
    const int n0 = blockIdx.x * 128;

    const __nv_bfloat16* ahi = g_ahi + c_AOFF[cluster] + (size_t)m0 * K;
    const __nv_bfloat16* alo = g_alo + c_AOFF[cluster] + (size_t)m0 * K;
    const __nv_bfloat16* bhi = g_bhi + c_BOFF[cluster] + (size_t)n0 * K;
    const __nv_bfloat16* blo = g_blo + c_BOFF[cluster] + (size_t)n0 * K;

    const int tid  = threadIdx.x;
    const int lane = tid & 31;
    const int wid  = tid >> 5;
    const int mwarp = (wid & 3) * 32;
    const int nwarp = (wid >> 2) * 64;

    const int nchunks = (K + 31) >> 5;

    auto issue = [&](int ic) {
        const int k0 = ic << 5;
        const uint32_t bo = sb + (uint32_t)(ic % NS) * STG_STRIDE;
        if (K - k0 >= 32) {
            for (int ci = tid; ci < 1024; ci += NTHREADS) {
                const int row = ci >> 3;
                const int g = ci & 7;
                const uint32_t sw = (uint32_t)((row * 128 + g * 16) ^ ((row & 7) << 4));
                const size_t src = (size_t)row * K + k0 + (g & 3) * 8;
                cp16(bo + STG_A + sw, ((g < 4) ? ahi : alo) + src);
                cp16(bo + STG_B + sw, ((g < 4) ? bhi : blo) + src);
            }
        } else {
            for (int ci = tid; ci < 512; ci += NTHREADS) {
                const int row = ci >> 2;
                const int rem = ci & 3;
                const int h = rem >> 1;
                const int j = rem & 1;
                const int g = h * 4 + j;
                const uint32_t sw = (uint32_t)((row * 128 + g * 16) ^ ((row & 7) << 4));
                const size_t src = (size_t)row * K + k0 + j * 8;
                cp16(bo + STG_A + sw, (h == 0 ? ahi : alo) + src);
                cp16(bo + STG_B + sw, (h == 0 ? bhi : blo) + src);
            }
        }
    };

    for (int s = 0; s < NS - 1; s++) {
        if (s < nchunks) issue(s);
        CP_COMMIT();
    }

    float acc[2][8][4] = {};

    // one k16-step of MMA work
    auto kstep = [&](const uint32_t bo, int ks) {
        const int arow = lane & 15;
        const int akb  = ks * 32 + (lane >> 4) * 16;
        uint32_t ah[2][4], al[2][4];
#pragma unroll
        for (int mt = 0; mt < 2; mt++) {
            const int row = mwarp + mt * 16 + arow;
            ldsm4(ah[mt], bswz(bo + STG_A, row, akb));
            ldsm4(al[mt], bswz(bo + STG_A, row, 64 + akb));
        }
        const int broff = (lane & 7) + ((lane >> 4) << 3);
        const int bkb   = ks * 32 + ((lane >> 3) & 1) * 16;
#pragma unroll
        for (int ng = 0; ng < 4; ng++) {
            uint32_t bh[4], bl[4];
            const int row = nwarp + ng * 16 + broff;
            ldsm4(bh, bswz(bo + STG_B, row, bkb));
            ldsm4(bl, bswz(bo + STG_B, row, 64 + bkb));
#pragma unroll
            for (int mt = 0; mt < 2; mt++) {
                mma_bf16(acc[mt][2 * ng + 0], ah[mt], bh[0], bh[1]);
                mma_bf16(acc[mt][2 * ng + 0], ah[mt], bl[0], bl[1]);
                mma_bf16(acc[mt][2 * ng + 0], al[mt], bh[0], bh[1]);
                mma_bf16(acc[mt][2 * ng + 1], ah[mt], bh[2], bh[3]);
                mma_bf16(acc[mt][2 * ng + 1], ah[mt], bl[2], bl[3]);
                mma_bf16(acc[mt][2 * ng + 1], al[mt], bh[2], bh[3]);
            }
        }
    };

    for (int ic = 0; ic < nchunks; ic++) {
        CP_WAIT1();
        __syncthreads();   // data visible + prior-iter compute done (guards reuse below)
        if (ic + NS - 1 < nchunks) issue(ic + NS - 1);
        CP_COMMIT();

        const int k0 = ic << 5;
        const uint32_t bo = sb + (uint32_t)(ic % NS) * STG_STRIDE;
        if (K - k0 >= 32) {
            kstep(bo, 0);
            kstep(bo, 1);
        } else {
            kstep(bo, 0);
        }
    }

    // epilogue: scale + scatter
#pragma unroll
    for (int mt = 0; mt < 2; mt++) {
        const int r0 = m0 + mwarp + mt * 16 + (lane >> 2);
        const int r1 = r0 + 8;
        float* q0 = nullptr;
        float* q1 = nullptr;
        if (r0 < cnt) q0 = out + (size_t)g_tok[cluster][r0] * D_PROJ + n0 + nwarp + (lane & 3) * 2;
        if (r1 < cnt) q1 = out + (size_t)g_tok[cluster][r1] * D_PROJ + n0 + nwarp + (lane & 3) * 2;
#pragma unroll
        for (int nt = 0; nt < 8; nt++) {
            if (q0) *reinterpret_cast<float2*>(q0 + nt * 8) =
                make_float2(acc[mt][nt][0] * EMB_SCALE, acc[mt][nt][1] * EMB_SCALE);
            if (q1) *reinterpret_cast<float2*>(q1 + nt * 8) =
                make_float2(acc[mt][nt][2] * EMB_SCALE, acc[mt][nt][3] * EMB_SCALE);
        }
    }
}

// ---------------- launch ----------------
extern "C" void kernel_launch(void* const* d_in, const int* in_sizes, int n_in,
                              void* d_out, int out_size) {
    const int* inp = (const int*)d_in[0];
    const float* emb[4];
    const float* proj[4];

    if (n_in >= 9 && in_sizes[2] == 1024 * 1024) {
        for (int i = 0; i < 4; i++) {
            emb[i]  = (const float*)d_in[1 + 2 * i];
            proj[i] = (const float*)d_in[2 + 2 * i];
        }
    } else {
        for (int i = 0; i < 4; i++) {
            emb[i]  = (const float*)d_in[1 + i];
            proj[i] = (const float*)d_in[5 + i];
        }
    }

    float* out = (float*)d_out;
    const int n_tok = in_sizes[0];

    cudaFuncSetAttribute(gemm_mma_kernel,
                         cudaFuncAttributeMaxDynamicSharedMemorySize, SMEM_BYTES);

    zero_kernel<<<1, 32>>>();
    bucket_kernel<<<(n_tok + 255) / 256, 256>>>(inp, n_tok);
    conv_kernel<<<dim3(148, 8), 256>>>(emb[0], emb[1], emb[2], emb[3],
                                       proj[0], proj[1], proj[2], proj[3]);

    dim3 grid(D_PROJ / 128, MAX_TILES);
    gemm_mma_kernel<<<grid, NTHREADS, SMEM_BYTES>>>(out);
}

// round 11
// speedup vs baseline: 1.5884x; 1.0473x over previous
#include <cuda_runtime.h>
#include <cuda_bf16.h>
#include <stdint.h>

#define N_TOKENS_TOTAL 16384
#define D_PROJ 1024
#define EMB_SCALE 32.0f
#define MAX_TILES 136
#define NTHREADS 256
#define NS 3

// ---------------- scratch ----------------
__device__ int g_cnt[4];
__device__ int g_tok[4][N_TOKENS_TOTAL];
__device__ int g_loc[4][N_TOKENS_TOTAL];
__device__ int g_tile_c[MAX_TILES];
__device__ int g_tile_m0[MAX_TILES];
__device__ int g_total_tiles;

// tf32 fragment-ordered scratch (f32 containers holding tf32 bits)
#define A_ELEMS (16384u * 1360u)
#define B_ELEMS (1024u * 1360u)
__device__ __align__(16) float g_a[A_ELEMS];
__device__ __align__(16) float g_b[B_ELEMS];

__constant__ int c_K[4]    = {1024, 256, 64, 16};
__constant__ int c_logK[4] = {10, 8, 6, 4};          // log2 K
__constant__ unsigned c_AOFF[4] = {0u, 16384u*1024u, 16384u*1280u, 16384u*1344u};
__constant__ unsigned c_BOFF[4] = {0u, 1024u*1024u, 1024u*1280u, 1024u*1344u};

// ---------------- helpers ----------------
__device__ __forceinline__ uint32_t smem_u32(const void* p) {
    uint32_t a;
    asm("{ .reg .u64 t; cvta.to.shared.u64 t, %1; cvt.u32.u64 %0, t; }" : "=r"(a) : "l"(p));
    return a;
}
__device__ __forceinline__ uint32_t f2tf(float x) {
    uint32_t r;
    asm("cvt.rna.tf32.f32 %0, %1;" : "=r"(r) : "f"(x));
    return r;
}
__device__ __forceinline__ void mma_tf32(float* c, const uint32_t* a,
                                         uint32_t b0, uint32_t b1) {
    asm volatile(
        "mma.sync.aligned.m16n8k8.row.col.f32.tf32.tf32.f32 "
        "{%0,%1,%2,%3}, {%4,%5,%6,%7}, {%8,%9}, {%0,%1,%2,%3};"
        : "+f"(c[0]), "+f"(c[1]), "+f"(c[2]), "+f"(c[3])
        : "r"(a[0]), "r"(a[1]), "r"(a[2]), "r"(a[3]), "r"(b0), "r"(b1));
}
__device__ __forceinline__ void lds128(uint32_t* r, uint32_t addr) {
    asm volatile("ld.shared.v4.b32 {%0,%1,%2,%3}, [%4];"
                 : "=r"(r[0]), "=r"(r[1]), "=r"(r[2]), "=r"(r[3]) : "r"(addr));
}
__device__ __forceinline__ void cp16(uint32_t dst, const void* src) {
    asm volatile("cp.async.cg.shared.global [%0], [%1], 16;"
                 :: "r"(dst), "l"(src) : "memory");
}
#define CP_COMMIT() asm volatile("cp.async.commit_group;" ::: "memory")
#define CP_WAIT1()  asm volatile("cp.async.wait_group 1;" ::: "memory")

// ---------------- kernel 1: zero ----------------
__global__ void zero_kernel() {
    if (threadIdx.x < 4) g_cnt[threadIdx.x] = 0;
}

// ---------------- kernel 2: bucket (block-aggregated atomics) ----------------
__global__ void bucket_kernel(const int* __restrict__ inp, int n) {
    __shared__ int s_cnt[4];
    __shared__ int s_base[4];
    const int t = blockIdx.x * blockDim.x + threadIdx.x;
    if (threadIdx.x < 4) s_cnt[threadIdx.x] = 0;
    __syncthreads();
    int v = 0, c = 0, l = 0, rank = 0;
    const bool valid = t < n;
    if (valid) {
        v = inp[t];
        if (v < 20000)       { c = 0; l = 0; }
        else if (v < 40000)  { c = 1; l = 20000; }
        else if (v < 200000) { c = 2; l = 40000; }
        else                 { c = 3; l = 200000; }
        rank = atomicAdd(&s_cnt[c], 1);
    }
    __syncthreads();
    if (threadIdx.x < 4)
        s_base[threadIdx.x] = atomicAdd(&g_cnt[threadIdx.x], s_cnt[threadIdx.x]);
    __syncthreads();
    if (valid) {
        const int p = s_base[c] + rank;
        g_tok[c][p] = t;
        g_loc[c][p] = v - l;
    }
}

// ---------------- kernel 3: fused tf32 fragment-layout conversion + plan ----------------
// A layout: [mtile][k16][st(8)][k8r(2)][lane(32)][4]  (per-lane a0..a3 of m16n8k8)
// B layout: [ntile(128)][k16][lane(32)][4]            (b0,b1 of k8a then k8b)
__global__ void conv_kernel(
    const float* __restrict__ e0, const float* __restrict__ e1,
    const float* __restrict__ e2, const float* __restrict__ e3,
    const float* __restrict__ p0, const float* __restrict__ p1,
    const float* __restrict__ p2, const float* __restrict__ p3)
{
    if (blockIdx.y == 0 && blockIdx.x == 0) {
        __shared__ int offs[5];
        if (threadIdx.x == 0) {
            offs[0] = 0;
            for (int c = 0; c < 4; c++) offs[c + 1] = offs[c] + ((g_cnt[c] + 127) >> 7);
            g_total_tiles = offs[4];
        }
        __syncthreads();
        const int total = offs[4];
        for (int i = threadIdx.x; i < total; i += blockDim.x) {
            int c = 0;
            while (i >= offs[c + 1]) c++;
            g_tile_c[i] = c;
            g_tile_m0[i] = (i - offs[c]) << 7;
        }
    }

    const int y = blockIdx.y;
    const unsigned stride = gridDim.x * blockDim.x;
    const unsigned t0 = blockIdx.x * blockDim.x + threadIdx.x;

    if (y < 4) {
        // ---- B: proj -> tf32 fragment order ----
        const int c = y;
        const float* proj = c == 0 ? p0 : c == 1 ? p1 : c == 2 ? p2 : p3;
        const int K = c_K[c];
        const int lkk = c_logK[c] - 4;                 // log2(K/16)
        const unsigned base = c_BOFF[c];
        const unsigned nu = (unsigned)(K >> 4) << 12;  // 128 ntiles * k16 * 32 lanes
        for (unsigned u = t0; u < nu; u += stride) {
            const int lane = u & 31;
            const int k16  = (u >> 5) & ((1u << lkk) - 1);
            const int nt   = u >> (5 + lkk);
            const int n    = nt * 8 + (lane >> 2);
            const int cb   = k16 * 16 + (lane & 3);
            const float* p = proj + (size_t)n * K + cb;
            uint4 v = make_uint4(f2tf(p[0]), f2tf(p[4]), f2tf(p[8]), f2tf(p[12]));
            *reinterpret_cast<uint4*>(g_b + base + ((size_t)u << 2)) = v;
        }
    } else {
        // ---- A: gathered emb -> compacted tf32 fragment order ----
        const int c = y - 4;
        const float* emb = c == 0 ? e0 : c == 1 ? e1 : c == 2 ? e2 : e3;
        const int K = c_K[c];
        const int lkk = c_logK[c] - 4;
        const int cnt = g_cnt[c];
        const unsigned base = c_AOFF[c];
        const int mtiles = (cnt + 127) >> 7;
        const unsigned nu = (unsigned)mtiles * ((unsigned)(K >> 4) << 9);
        for (unsigned u = t0; u < nu; u += stride) {
            const int lane  = u & 31;
            const int k8r   = (u >> 5) & 1;
            const int st    = (u >> 6) & 7;
            const int k16   = (u >> 9) & ((1u << lkk) - 1);
            const int mtile = u >> (9 + lkk);
            const int r0 = mtile * 128 + st * 16 + (lane >> 2);
            const int r1 = r0 + 8;
            const int cb = k16 * 16 + k8r * 8 + (lane & 3);
            float x0 = 0.f, x1 = 0.f, x2 = 0.f, x3 = 0.f;
            if (r0 < cnt) {
                const float* p = emb + (size_t)g_loc[c][r0] * K + cb;
                x0 = p[0]; x2 = p[4];
            }
            if (r1 < cnt) {
                const float* p = emb + (size_t)g_loc[c][r1] * K + cb;
                x1 = p[0]; x3 = p[4];
            }
            uint4 v = make_uint4(f2tf(x0), f2tf(x1), f2tf(x2), f2tf(x3));
            *reinterpret_cast<uint4*>(g_a + base + ((size_t)u << 2)) = v;
        }
    }
}

// ---------------- kernel 4: tf32 cp.async-pipelined GEMM ----------------
// BK=32 (2 k16). Stage: A 16KB + B 16KB = 32KB; NS=3 -> 96KB, 2 CTA/SM.
#define STG_A 0
#define STG_B 16384
#define STG_STRIDE 32768
#define SMEM_BYTES (NS * STG_STRIDE)

__global__ __launch_bounds__(NTHREADS, 2) void gemm_mma_kernel(float* __restrict__ out) {
    extern __shared__ char smem[];
    const uint32_t sb = smem_u32(smem);

    const int tile = blockIdx.y;
    if (tile >= g_total_tiles) return;

    const int cluster = g_tile_c[tile];
    const int m0 = g_tile_m0[tile];
    const int cnt = g_cnt[cluster];
    const int K = c_K[cluster];
    const int lkk = c_logK[cluster] - 4;     // log2(K/16)
    const int n0 = blockIdx.x * 128;

    const float* abase = g_a + c_AOFF[cluster] + (size_t)m0 * K;  // mtile stride = 128*K
    const float* bbase = g_b + c_BOFF[cluster];
    const int ntg0 = n0 >> 3;

    const int tid  = threadIdx.x;
    const int lane = tid & 31;
    const int wid  = tid >> 5;

    const int nchunks = (K + 31) >> 5;

    auto issue = [&](int ic) {
        const int k16a = ic << 1;
        const int nk16 = ((K >> 4) - k16a) >= 2 ? 2 : 1;
        const uint32_t bo = sb + (uint32_t)(ic % NS) * STG_STRIDE;
        // A: contiguous nk16*8KB
        const float* asrc = abase + ((size_t)k16a << 11);
        const int agr = nk16 << 9;
        for (int ci = tid; ci < agr; ci += NTHREADS)
            cp16(bo + STG_A + ci * 16, asrc + ci * 4);
        // B: 16 ntiles, each contiguous nk16*512B
        const int lgb = 5 + (nk16 >> 1);     // per-ntile granules: 32 or 64
        const int bgr = nk16 << 9;
        for (int ci = tid; ci < bgr; ci += NTHREADS) {
            const int nt = ci >> lgb;
            const int rem = ci & ((1 << lgb) - 1);
            const float* bsrc =
                bbase + ((((size_t)(ntg0 + nt) << lkk) + k16a) << 7) + rem * 4;
            cp16(bo + STG_B + (nt << (lgb + 4)) + (rem << 4), bsrc);
        }
    };

    for (int s = 0; s < NS - 1; s++) {
        if (s < nchunks) issue(s);
        CP_COMMIT();
    }

    float acc[2][8][4] = {};

    auto kstep = [&](uint32_t bo, int k16r, int bstr) {
        uint32_t aA[2][4], aB[2][4];
#pragma unroll
        for (int mt = 0; mt < 2; mt++) {
            const int st = (wid & 3) * 2 + mt;
            const uint32_t ad = bo + STG_A + k16r * 8192 + st * 1024 + lane * 16;
            lds128(aA[mt], ad);
            lds128(aB[mt], ad + 512);
        }
#pragma unroll
        for (int nt = 0; nt < 8; nt++) {
            const int ntb = (wid >> 2) * 8 + nt;
            uint32_t b[4];
            lds128(b, bo + STG_B + ntb * bstr + k16r * 512 + lane * 16);
#pragma unroll
            for (int mt = 0; mt < 2; mt++) {
                mma_tf32(acc[mt][nt], aA[mt], b[0], b[1]);
                mma_tf32(acc[mt][nt], aB[mt], b[2], b[3]);
            }
        }
    };

    for (int ic = 0; ic < nchunks; ic++) {
        CP_WAIT1();
        __syncthreads();
        if (ic + NS - 1 < nchunks) issue(ic + NS - 1);
        CP_COMMIT();

        const int nk16 = ((K >> 4) - (ic << 1)) >= 2 ? 2 : 1;
        const int bstr = nk16 << 9;
        const uint32_t bo = sb + (uint32_t)(ic % NS) * STG_STRIDE;
        kstep(bo, 0, bstr);
        if (nk16 == 2) kstep(bo, 1, bstr);
    }

    // epilogue: scale + scatter
#pragma unroll
    for (int mt = 0; mt < 2; mt++) {
        const int r0 = m0 + (wid & 3) * 32 + mt * 16 + (lane >> 2);
        const int r1 = r0 + 8;
        const int ncol = n0 + (wid >> 2) * 64 + (lane & 3) * 2;
        float* q0 = nullptr;
        float* q1 = nullptr;
        if (r0 < cnt) q0 = out + (size_t)g_tok[cluster][r0] * D_PROJ + ncol;
        if (r1 < cnt) q1 = out + (size_t)g_tok[cluster][r1] * D_PROJ + ncol;
#pragma unroll
        for (int nt = 0; nt < 8; nt++) {
            if (q0) *reinterpret_cast<float2*>(q0 + nt * 8) =
                make_float2(acc[mt][nt][0] * EMB_SCALE, acc[mt][nt][1] * EMB_SCALE);
            if (q1) *reinterpret_cast<float2*>(q1 + nt * 8) =
                make_float2(acc[mt][nt][2] * EMB_SCALE, acc[mt][nt][3] * EMB_SCALE);
        }
    }
}

// ---------------- launch ----------------
extern "C" void kernel_launch(void* const* d_in, const int* in_sizes, int n_in,
                              void* d_out, int out_size) {
    const int* inp = (const int*)d_in[0];
    const float* emb[4];
    const float* proj[4];

    if (n_in >= 9 && in_sizes[2] == 1024 * 1024) {
        for (int i = 0; i < 4; i++) {
            emb[i]  = (const float*)d_in[1 + 2 * i];
            proj[i] = (const float*)d_in[2 + 2 * i];
        }
    } else {
        for (int i = 0; i < 4; i++) {
            emb[i]  = (const float*)d_in[1 + i];
            proj[i] = (const float*)d_in[5 + i];
        }
    }

    float* out = (float*)d_out;
    const int n_tok = in_sizes[0];

    cudaFuncSetAttribute(gemm_mma_kernel,
                         cudaFuncAttributeMaxDynamicSharedMemorySize, SMEM_BYTES);

    zero_kernel<<<1, 32>>>();
    bucket_kernel<<<(n_tok + 255) / 256, 256>>>(inp, n_tok);
    conv_kernel<<<dim3(148, 8), 256>>>(emb[0], emb[1], emb[2], emb[3],
                                       proj[0], proj[1], proj[2], proj[3]);

    dim3 grid(D_PROJ / 128, MAX_TILES);
    gemm_mma_kernel<<<grid, NTHREADS, SMEM_BYTES>>>(out);
}

// round 12
// speedup vs baseline: 1.6706x; 1.0518x over previous
#include <cuda_runtime.h>
#include <cuda_bf16.h>
#include <stdint.h>

#define N_TOKENS_TOTAL 16384
#define D_PROJ 1024
#define EMB_SCALE 32.0f
#define MAX_TILES 136
#define NTHREADS 256
#define NS 3

// ---------------- scratch ----------------
__device__ int g_cnt[4];
__device__ int g_tok[4][N_TOKENS_TOTAL];
__device__ int g_loc[4][N_TOKENS_TOTAL];
__device__ int g_tile_c[MAX_TILES];
__device__ int g_tile_m0[MAX_TILES];
__device__ int g_total_tiles;

// tf32 fragment-ordered scratch (f32 containers holding tf32 bits)
#define A_ELEMS (16384u * 1360u)
#define B_ELEMS (1024u * 1360u)
__device__ __align__(16) float g_a[A_ELEMS];
__device__ __align__(16) float g_b[B_ELEMS];

__constant__ int c_K[4]    = {1024, 256, 64, 16};
__constant__ int c_logK[4] = {10, 8, 6, 4};          // log2 K
__constant__ unsigned c_AOFF[4] = {0u, 16384u*1024u, 16384u*1280u, 16384u*1344u};
__constant__ unsigned c_BOFF[4] = {0u, 1024u*1024u, 1024u*1280u, 1024u*1344u};

// ---------------- helpers ----------------
__device__ __forceinline__ uint32_t smem_u32(const void* p) {
    uint32_t a;
    asm("{ .reg .u64 t; cvta.to.shared.u64 t, %1; cvt.u32.u64 %0, t; }" : "=r"(a) : "l"(p));
    return a;
}
__device__ __forceinline__ uint32_t f2tf(float x) {
    uint32_t r;
    asm("cvt.rna.tf32.f32 %0, %1;" : "=r"(r) : "f"(x));
    return r;
}
__device__ __forceinline__ void mma_tf32(float* c, const uint32_t* a,
                                         uint32_t b0, uint32_t b1) {
    asm volatile(
        "mma.sync.aligned.m16n8k8.row.col.f32.tf32.tf32.f32 "
        "{%0,%1,%2,%3}, {%4,%5,%6,%7}, {%8,%9}, {%0,%1,%2,%3};"
        : "+f"(c[0]), "+f"(c[1]), "+f"(c[2]), "+f"(c[3])
        : "r"(a[0]), "r"(a[1]), "r"(a[2]), "r"(a[3]), "r"(b0), "r"(b1));
}
__device__ __forceinline__ void lds128(uint32_t* r, uint32_t addr) {
    asm volatile("ld.shared.v4.b32 {%0,%1,%2,%3}, [%4];"
                 : "=r"(r[0]), "=r"(r[1]), "=r"(r[2]), "=r"(r[3]) : "r"(addr));
}
__device__ __forceinline__ void cp16(uint32_t dst, const void* src) {
    asm volatile("cp.async.cg.shared.global [%0], [%1], 16;"
                 :: "r"(dst), "l"(src) : "memory");
}
#define CP_COMMIT() asm volatile("cp.async.commit_group;" ::: "memory")
#define CP_WAIT1()  asm volatile("cp.async.wait_group 1;" ::: "memory")

// ---------------- kernel 1: zero ----------------
__global__ void zero_kernel() {
    if (threadIdx.x < 4) g_cnt[threadIdx.x] = 0;
}

// ---------------- kernel 2: bucket (block-aggregated atomics) ----------------
__global__ void bucket_kernel(const int* __restrict__ inp, int n) {
    __shared__ int s_cnt[4];
    __shared__ int s_base[4];
    const int t = blockIdx.x * blockDim.x + threadIdx.x;
    if (threadIdx.x < 4) s_cnt[threadIdx.x] = 0;
    __syncthreads();
    int v = 0, c = 0, l = 0, rank = 0;
    const bool valid = t < n;
    if (valid) {
        v = inp[t];
        if (v < 20000)       { c = 0; l = 0; }
        else if (v < 40000)  { c = 1; l = 20000; }
        else if (v < 200000) { c = 2; l = 40000; }
        else                 { c = 3; l = 200000; }
        rank = atomicAdd(&s_cnt[c], 1);
    }
    __syncthreads();
    if (threadIdx.x < 4)
        s_base[threadIdx.x] = atomicAdd(&g_cnt[threadIdx.x], s_cnt[threadIdx.x]);
    __syncthreads();
    if (valid) {
        const int p = s_base[c] + rank;
        g_tok[c][p] = t;
        g_loc[c][p] = v - l;
    }
}

// ---------------- kernel 3: fused tf32 fragment-layout conversion + plan ----------------
// A layout: [mtile][k16][st(8)][k8r(2)][lane(32)][4]
// B layout: [ntile(128)][k16][lane(32)][4]
__global__ void conv_kernel(
    const float* __restrict__ e0, const float* __restrict__ e1,
    const float* __restrict__ e2, const float* __restrict__ e3,
    const float* __restrict__ p0, const float* __restrict__ p1,
    const float* __restrict__ p2, const float* __restrict__ p3)
{
    if (blockIdx.y == 0 && blockIdx.x == 0) {
        __shared__ int offs[5];
        if (threadIdx.x == 0) {
            offs[0] = 0;
            for (int c = 0; c < 4; c++) offs[c + 1] = offs[c] + ((g_cnt[c] + 127) >> 7);
            g_total_tiles = offs[4];
        }
        __syncthreads();
        const int total = offs[4];
        for (int i = threadIdx.x; i < total; i += blockDim.x) {
            int c = 0;
            while (i >= offs[c + 1]) c++;
            g_tile_c[i] = c;
            g_tile_m0[i] = (i - offs[c]) << 7;
        }
    }

    const int y = blockIdx.y;
    const unsigned stride = gridDim.x * blockDim.x;
    const unsigned t0 = blockIdx.x * blockDim.x + threadIdx.x;

    if (y < 4) {
        const int c = y;
        const float* proj = c == 0 ? p0 : c == 1 ? p1 : c == 2 ? p2 : p3;
        const int K = c_K[c];
        const int lkk = c_logK[c] - 4;
        const unsigned base = c_BOFF[c];
        const unsigned nu = (unsigned)(K >> 4) << 12;
        for (unsigned u = t0; u < nu; u += stride) {
            const int lane = u & 31;
            const int k16  = (u >> 5) & ((1u << lkk) - 1);
            const int nt   = u >> (5 + lkk);
            const int n    = nt * 8 + (lane >> 2);
            const int cb   = k16 * 16 + (lane & 3);
            const float* p = proj + (size_t)n * K + cb;
            uint4 v = make_uint4(f2tf(p[0]), f2tf(p[4]), f2tf(p[8]), f2tf(p[12]));
            *reinterpret_cast<uint4*>(g_b + base + ((size_t)u << 2)) = v;
        }
    } else {
        const int c = y - 4;
        const float* emb = c == 0 ? e0 : c == 1 ? e1 : c == 2 ? e2 : e3;
        const int K = c_K[c];
        const int lkk = c_logK[c] - 4;
        const int cnt = g_cnt[c];
        const unsigned base = c_AOFF[c];
        const int mtiles = (cnt + 127) >> 7;
        const unsigned nu = (unsigned)mtiles * ((unsigned)(K >> 4) << 9);
        for (unsigned u = t0; u < nu; u += stride) {
            const int lane  = u & 31;
            const int k8r   = (u >> 5) & 1;
            const int st    = (u >> 6) & 7;
            const int k16   = (u >> 9) & ((1u << lkk) - 1);
            const int mtile = u >> (9 + lkk);
            const int r0 = mtile * 128 + st * 16 + (lane >> 2);
            const int r1 = r0 + 8;
            const int cb = k16 * 16 + k8r * 8 + (lane & 3);
            float x0 = 0.f, x1 = 0.f, x2 = 0.f, x3 = 0.f;
            if (r0 < cnt) {
                const float* p = emb + (size_t)g_loc[c][r0] * K + cb;
                x0 = p[0]; x2 = p[4];
            }
            if (r1 < cnt) {
                const float* p = emb + (size_t)g_loc[c][r1] * K + cb;
                x1 = p[0]; x3 = p[4];
            }
            uint4 v = make_uint4(f2tf(x0), f2tf(x1), f2tf(x2), f2tf(x3));
            *reinterpret_cast<uint4*>(g_a + base + ((size_t)u << 2)) = v;
        }
    }
}

// ---------------- kernel 4: tf32 cp.async-pipelined GEMM ----------------
// BM=128, BN=64, BK=32. Stage: A 16KB + B 8KB = 24KB; NS=3 -> 72KB; 3 CTAs/SM.
#define STG_A 0
#define STG_B 16384
#define STG_STRIDE 24576
#define SMEM_BYTES (NS * STG_STRIDE)

__global__ __launch_bounds__(NTHREADS, 3) void gemm_mma_kernel(float* __restrict__ out) {
    extern __shared__ char smem[];
    const uint32_t sb = smem_u32(smem);

    const int tile = blockIdx.y;
    if (tile >= g_total_tiles) return;

    const int cluster = g_tile_c[tile];
    const int m0 = g_tile_m0[tile];
    const int cnt = g_cnt[cluster];
    const int K = c_K[cluster];
    const int lkk = c_logK[cluster] - 4;
    const int n0 = blockIdx.x * 64;

    const float* abase = g_a + c_AOFF[cluster] + (size_t)m0 * K;
    const float* bbase = g_b + c_BOFF[cluster];
    const int ntg0 = n0 >> 3;     // 8 ntiles per block

    const int tid  = threadIdx.x;
    const int lane = tid & 31;
    const int wid  = tid >> 5;

    const int nchunks = (K + 31) >> 5;

    auto issue = [&](int ic) {
        const int k16a = ic << 1;
        const int nk16 = ((K >> 4) - k16a) >= 2 ? 2 : 1;
        const uint32_t bo = sb + (uint32_t)(ic % NS) * STG_STRIDE;
        // A: contiguous nk16*8KB
        const float* asrc = abase + ((size_t)k16a << 11);
        const int agr = nk16 << 9;
        for (int ci = tid; ci < agr; ci += NTHREADS)
            cp16(bo + STG_A + ci * 16, asrc + ci * 4);
        // B: 8 ntiles, each contiguous nk16*512B
        const int lgb = 5 + (nk16 >> 1);
        const int bgr = nk16 << 8;
        for (int ci = tid; ci < bgr; ci += NTHREADS) {
            const int nt = ci >> lgb;
            const int rem = ci & ((1 << lgb) - 1);
            const float* bsrc =
                bbase + ((((size_t)(ntg0 + nt) << lkk) + k16a) << 7) + rem * 4;
            cp16(bo + STG_B + (nt << (lgb + 4)) + (rem << 4), bsrc);
        }
    };

    for (int s = 0; s < NS - 1; s++) {
        if (s < nchunks) issue(s);
        CP_COMMIT();
    }

    float acc[2][4][4] = {};

    auto kstep = [&](uint32_t bo, int k16r, int bstr) {
        uint32_t aA[2][4], aB[2][4];
#pragma unroll
        for (int mt = 0; mt < 2; mt++) {
            const int st = (wid & 3) * 2 + mt;
            const uint32_t ad = bo + STG_A + k16r * 8192 + st * 1024 + lane * 16;
            lds128(aA[mt], ad);
            lds128(aB[mt], ad + 512);
        }
#pragma unroll
        for (int nt = 0; nt < 4; nt++) {
            const int ntb = (wid >> 2) * 4 + nt;
            uint32_t b[4];
            lds128(b, bo + STG_B + ntb * bstr + k16r * 512 + lane * 16);
#pragma unroll
            for (int mt = 0; mt < 2; mt++) {
                mma_tf32(acc[mt][nt], aA[mt], b[0], b[1]);
                mma_tf32(acc[mt][nt], aB[mt], b[2], b[3]);
            }
        }
    };

    for (int ic = 0; ic < nchunks; ic++) {
        CP_WAIT1();
        __syncthreads();
        if (ic + NS - 1 < nchunks) issue(ic + NS - 1);
        CP_COMMIT();

        const int nk16 = ((K >> 4) - (ic << 1)) >= 2 ? 2 : 1;
        const int bstr = nk16 << 9;
        const uint32_t bo = sb + (uint32_t)(ic % NS) * STG_STRIDE;
        kstep(bo, 0, bstr);
        if (nk16 == 2) kstep(bo, 1, bstr);
    }

    // epilogue: scale + scatter
#pragma unroll
    for (int mt = 0; mt < 2; mt++) {
        const int r0 = m0 + (wid & 3) * 32 + mt * 16 + (lane >> 2);
        const int r1 = r0 + 8;
        const int ncol = n0 + (wid >> 2) * 32 + (lane & 3) * 2;
        float* q0 = nullptr;
        float* q1 = nullptr;
        if (r0 < cnt) q0 = out + (size_t)g_tok[cluster][r0] * D_PROJ + ncol;
        if (r1 < cnt) q1 = out + (size_t)g_tok[cluster][r1] * D_PROJ + ncol;
#pragma unroll
        for (int nt = 0; nt < 4; nt++) {
            if (q0) *reinterpret_cast<float2*>(q0 + nt * 8) =
                make_float2(acc[mt][nt][0] * EMB_SCALE, acc[mt][nt][1] * EMB_SCALE);
            if (q1) *reinterpret_cast<float2*>(q1 + nt * 8) =
                make_float2(acc[mt][nt][2] * EMB_SCALE, acc[mt][nt][3] * EMB_SCALE);
        }
    }
}

// ---------------- launch ----------------
extern "C" void kernel_launch(void* const* d_in, const int* in_sizes, int n_in,
                              void* d_out, int out_size) {
    const int* inp = (const int*)d_in[0];
    const float* emb[4];
    const float* proj[4];

    if (n_in >= 9 && in_sizes[2] == 1024 * 1024) {
        for (int i = 0; i < 4; i++) {
            emb[i]  = (const float*)d_in[1 + 2 * i];
            proj[i] = (const float*)d_in[2 + 2 * i];
        }
    } else {
        for (int i = 0; i < 4; i++) {
            emb[i]  = (const float*)d_in[1 + i];
            proj[i] = (const float*)d_in[5 + i];
        }
    }

    float* out = (float*)d_out;
    const int n_tok = in_sizes[0];

    cudaFuncSetAttribute(gemm_mma_kernel,
                         cudaFuncAttributeMaxDynamicSharedMemorySize, SMEM_BYTES);

    zero_kernel<<<1, 32>>>();
    bucket_kernel<<<(n_tok + 255) / 256, 256>>>(inp, n_tok);
    conv_kernel<<<dim3(148, 8), 256>>>(emb[0], emb[1], emb[2], emb[3],
                                       proj[0], proj[1], proj[2], proj[3]);

    dim3 grid(D_PROJ / 64, MAX_TILES);
    gemm_mma_kernel<<<grid, NTHREADS, SMEM_BYTES>>>(out);
}